// round 6
// baseline (speedup 1.0000x reference)
#include <cuda_runtime.h>
#include <cuda_bf16.h>
#include <math.h>

// Problem constants
constexpr int kT = 386;       // LSTM positions (SENT_LEN + 2)
constexpr int kH = 512;       // hidden dim
constexpr int kG = 2048;      // 4*H gates
constexpr int kE = 1024;      // enc dim (2H)
constexpr int kS = 73920;     // number of spans = 385*384/2

// ---------------- scratch (device globals; no allocation) ----------------
__device__ float g_x [kT * kH];           // embedded input [T,512]
__device__ float g_gx[2 * kT * kG];       // x@Wih^T + b per direction [2][T][2048]
__device__ float g_h [2 * kT * kH];       // fwd/bwd hidden states [2][T][512]
__device__ float g_A1[2 * kT * kE];       // fwd@W1_top / bwd@W1_bot  [2][T][1024]
__device__ float g_Av[2 * kT * kE];       // fwd@V1_top / bwd@V1_bot  [2][T][1024]
__device__ int   g_L[kS];
__device__ int   g_R[kS];
__device__ unsigned g_bar[64];            // per-direction barrier, 128B apart (idx 0, 32)

// ---------------- fast math helpers ----------------
__device__ __forceinline__ float fast_ex2(float x) {
    float r; asm("ex2.approx.ftz.f32 %0, %1;" : "=f"(r) : "f"(x)); return r;
}
__device__ __forceinline__ float fast_rcp(float x) {
    float r; asm("rcp.approx.ftz.f32 %0, %1;" : "=f"(r) : "f"(x)); return r;
}
__device__ __forceinline__ float fsig(float x) {
    return fast_rcp(1.f + fast_ex2(-1.44269504f * x));
}
__device__ __forceinline__ float ftanh(float x) {
    return fmaf(2.f, fsig(2.f * x), -1.f);
}

// packed fp32x2 helpers (Blackwell FFMA2)
__device__ __forceinline__ unsigned long long fma_f32x2(unsigned long long a,
                                                        unsigned long long b,
                                                        unsigned long long c) {
    unsigned long long d;
    asm("fma.rn.f32x2 %0, %1, %2, %3;" : "=l"(d) : "l"(a), "l"(b), "l"(c));
    return d;
}
__device__ __forceinline__ unsigned long long pack2(float lo, float hi) {
    unsigned long long d;
    asm("mov.b64 %0, {%1, %2};" : "=l"(d) : "f"(lo), "f"(hi));
    return d;
}
__device__ __forceinline__ float2 unpack2(unsigned long long v) {
    float lo, hi;
    asm("mov.b64 {%0, %1}, %2;" : "=f"(lo), "=f"(hi) : "l"(v));
    return make_float2(lo, hi);
}

// ---------------- init: embeddings gather + span index tables + barrier reset ----
__global__ void init_kernel(const int* __restrict__ tag_ids,
                            const int* __restrict__ word_ids,
                            const float* __restrict__ tag_emb,
                            const float* __restrict__ word_emb)
{
    int b = blockIdx.x, tid = threadIdx.x;
    if (b == 0 && tid < 2) g_bar[tid * 32] = 0u;
    if (b < kT) {
        int t = b;
        int tg = tag_ids[t], wd = word_ids[t];
        for (int i = tid; i < kH; i += 256) {
            float v = (i < 128) ? tag_emb[tg * 128 + i] : word_emb[wd * 384 + (i - 128)];
            g_x[t * kH + i] = v;
        }
    } else {
        int s = (b - kT) * 256 + tid;
        if (s < kS) {
            // invert triangular index: off(l) = (769*l - l*l)/2
            int l = (int)((769.0 - sqrt((double)(591361 - 8 * s))) * 0.5);
            if (l < 0) l = 0; if (l > 383) l = 383;
            while (l < 383 && (769 * (l + 1) - (l + 1) * (l + 1)) / 2 <= s) l++;
            while (l > 0 && (769 * l - l * l) / 2 > s) l--;
            int off = (769 * l - l * l) / 2;
            g_L[s] = l;
            g_R[s] = l + 1 + (s - off);
        }
    }
}

// ---------------- gx GEMM: gx[dir] = x @ Wih^T + b   (NT layout) ----------------
// M=386, N=2048, K=512. A=[M,K] row-major, B=[N,K] row-major.
__global__ __launch_bounds__(256) void gx_gemm(const float* __restrict__ Wf,
                                               const float* __restrict__ bfv,
                                               const float* __restrict__ Wb,
                                               const float* __restrict__ bbv)
{
    int dir = blockIdx.z;
    const float* B    = dir ? Wb : Wf;
    const float* bias = dir ? bbv : bfv;
    const float* A = g_x;
    float* C = g_gx + (size_t)dir * kT * kG;

    int tid = threadIdx.x;
    int m0 = blockIdx.x * 64, n0 = blockIdx.y * 64;
    __shared__ __align__(16) float As[16][68];
    __shared__ __align__(16) float Bs[16][68];
    float acc[4][4] = {};
    int tx = tid & 15, ty = tid >> 4;

    for (int k0 = 0; k0 < kH; k0 += 16) {
        int mr = tid >> 2, kq = (tid & 3) * 4;
        int gm = m0 + mr;
        float4 va = (gm < kT) ? *(const float4*)&A[(size_t)gm * kH + k0 + kq]
                              : make_float4(0.f, 0.f, 0.f, 0.f);
        As[kq + 0][mr] = va.x; As[kq + 1][mr] = va.y;
        As[kq + 2][mr] = va.z; As[kq + 3][mr] = va.w;
        float4 vb = *(const float4*)&B[(size_t)(n0 + mr) * kH + k0 + kq];
        Bs[kq + 0][mr] = vb.x; Bs[kq + 1][mr] = vb.y;
        Bs[kq + 2][mr] = vb.z; Bs[kq + 3][mr] = vb.w;
        __syncthreads();
        #pragma unroll
        for (int k = 0; k < 16; k++) {
            float4 a = *(const float4*)&As[k][ty * 4];
            float4 bv = *(const float4*)&Bs[k][tx * 4];
            float av[4] = {a.x, a.y, a.z, a.w};
            float bw[4] = {bv.x, bv.y, bv.z, bv.w};
            #pragma unroll
            for (int i = 0; i < 4; i++)
                #pragma unroll
                for (int j = 0; j < 4; j++)
                    acc[i][j] = fmaf(av[i], bw[j], acc[i][j]);
        }
        __syncthreads();
    }
    #pragma unroll
    for (int i = 0; i < 4; i++) {
        int gm = m0 + ty * 4 + i;
        if (gm < kT) {
            #pragma unroll
            for (int j = 0; j < 4; j++) {
                int n = n0 + tx * 4 + j;
                C[(size_t)gm * kG + n] = acc[i][j] + bias[n];
            }
        }
    }
}

// ---------------- persistent bidirectional LSTM ----------------
// 64 CTAs: CTAs [0,32) = forward, [32,64) = backward. Each CTA owns 16 hidden
// units (64 gate rows); Whh slice lives in registers as packed f32x2 pairs.
// Per-direction release/acquire barrier; next-step gx prefetch issued before poll.
__global__ __launch_bounds__(512, 1) void lstm_kernel(const float* __restrict__ Wfhh,
                                                      const float* __restrict__ Wbhh)
{
    int tid = threadIdx.x;
    int dir = blockIdx.x >> 5;
    int cta = blockIdx.x & 31;
    int lr  = tid >> 3;      // local gate row 0..63
    int sl  = tid & 7;       // slice within row
    int gate = lr >> 4, u = lr & 15;
    int ug  = cta * 16 + u;
    int row = gate * kH + ug;

    const float* W = (dir ? Wbhh : Wfhh) + (size_t)row * kH;
    ulonglong2 w2r[16];
    int koff[16];
    #pragma unroll
    for (int m = 0; m < 16; m++) {
        int ko = sl * 64 + ((4 * m + 4 * sl) & 63);   // bank-rotated k offset
        koff[m] = ko;
        w2r[m] = *(const ulonglong2*)&W[ko];
    }

    __shared__ __align__(16) float sh_h[kH];
    __shared__ float sh_g[64];
    __shared__ float sh_c[16];
    if (tid < 16) sh_c[tid] = 0.f;

    float* hbase = g_h + (size_t)dir * kT * kH;
    const float* gxbase = g_gx + (size_t)dir * kT * kG;
    unsigned* bar = &g_bar[dir * 32];
    int ugl = cta * 16 + (tid & 15);

    // preload gx for step 0
    float4 gxv;
    {
        int t0 = dir ? (kT - 1) : 0;
        if (tid < 16) {
            const float* gx = gxbase + (size_t)t0 * kG + ugl;
            gxv.x = __ldcg(gx);
            gxv.y = __ldcg(gx + kH);
            gxv.z = __ldcg(gx + 2 * kH);
            gxv.w = __ldcg(gx + 3 * kH);
        }
    }

    for (int step = 0; step < kT; step++) {
        int t = dir ? (kT - 1 - step) : step;

        if (step == 0) {
            sh_h[tid] = 0.f;
        } else {
            int tp = dir ? t + 1 : t - 1;
            sh_h[tid] = __ldcg(&hbase[(size_t)tp * kH + tid]);
        }
        __syncthreads();

        // packed gemv: 4 independent f32x2 accumulator chains
        unsigned long long a0 = 0ull, a1 = 0ull, a2 = 0ull, a3 = 0ull;
        #pragma unroll
        for (int m = 0; m < 16; m += 2) {
            ulonglong2 h0 = *(const ulonglong2*)&sh_h[koff[m]];
            ulonglong2 h1 = *(const ulonglong2*)&sh_h[koff[m + 1]];
            a0 = fma_f32x2(w2r[m].x,     h0.x, a0);
            a1 = fma_f32x2(w2r[m].y,     h0.y, a1);
            a2 = fma_f32x2(w2r[m + 1].x, h1.x, a2);
            a3 = fma_f32x2(w2r[m + 1].y, h1.y, a3);
        }
        float2 f0 = unpack2(a0), f1 = unpack2(a1), f2 = unpack2(a2), f3 = unpack2(a3);
        float acc = ((f0.x + f0.y) + (f1.x + f1.y)) + ((f2.x + f2.y) + (f3.x + f3.y));
        acc += __shfl_down_sync(0xffffffffu, acc, 4, 8);
        acc += __shfl_down_sync(0xffffffffu, acc, 2, 8);
        acc += __shfl_down_sync(0xffffffffu, acc, 1, 8);
        if (sl == 0) sh_g[lr] = acc;
        __syncthreads();

        if (tid < 16) {
            float gi = gxv.x + sh_g[tid];
            float gf = gxv.y + sh_g[16 + tid];
            float gg = gxv.z + sh_g[32 + tid];
            float go = gxv.w + sh_g[48 + tid];
            float si = fsig(gi);
            float sf = fsig(gf);
            float so = fsig(go);
            float c = sf * sh_c[tid] + si * ftanh(gg);
            sh_c[tid] = c;
            float h = so * ftanh(c);
            __stcg(&hbase[(size_t)t * kH + ugl], h);
        }
        __syncthreads();

        if (step < kT - 1) {
            // issue next-step gx loads BEFORE the poll so L2 latency hides under it
            float4 gxn;
            if (tid < 16) {
                int tn = dir ? (t - 1) : (t + 1);
                const float* gx = gxbase + (size_t)tn * kG + ugl;
                gxn.x = __ldcg(gx);
                gxn.y = __ldcg(gx + kH);
                gxn.z = __ldcg(gx + 2 * kH);
                gxn.w = __ldcg(gx + 3 * kH);
            }
            if (tid == 0) {
                asm volatile("red.release.gpu.add.u32 [%0], %1;"
                             :: "l"(bar), "r"(1u) : "memory");
                unsigned tgt = (unsigned)(step + 1) * 32u;
                unsigned v;
                do {
                    asm volatile("ld.acquire.gpu.u32 %0, [%1];"
                                 : "=r"(v) : "l"(bar) : "memory");
                } while (v < tgt);
            }
            __syncthreads();
            gxv = gxn;
        }
    }
}

// ---------------- A-table GEMMs: A[dir] = h[dir] @ Wtab[dir_half]  (NN) --------
// M=386, N=1024, K=512. B=[K,N] row-major (n contiguous).
__global__ __launch_bounds__(256) void pre_gemm(const float* __restrict__ W1,
                                                const float* __restrict__ V1)
{
    int dir = blockIdx.z & 1, tab = blockIdx.z >> 1;
    const float* A = g_h + (size_t)dir * kT * kH;
    const float* B = (tab ? V1 : W1) + (size_t)dir * kH * kE;
    float* C = (tab ? g_Av : g_A1) + (size_t)dir * kT * kE;

    int tid = threadIdx.x;
    int m0 = blockIdx.x * 64, n0 = blockIdx.y * 64;
    __shared__ __align__(16) float As[16][68];
    __shared__ __align__(16) float Bs[16][68];
    float acc[4][4] = {};
    int tx = tid & 15, ty = tid >> 4;

    for (int k0 = 0; k0 < kH; k0 += 16) {
        {
            int mr = tid >> 2, kq = (tid & 3) * 4;
            int gm = m0 + mr;
            float4 va = (gm < kT) ? *(const float4*)&A[(size_t)gm * kH + k0 + kq]
                                  : make_float4(0.f, 0.f, 0.f, 0.f);
            As[kq + 0][mr] = va.x; As[kq + 1][mr] = va.y;
            As[kq + 2][mr] = va.z; As[kq + 3][mr] = va.w;
        }
        {
            int kr = tid >> 4, nq = (tid & 15) * 4;
            float4 vb = *(const float4*)&B[(size_t)(k0 + kr) * kE + n0 + nq];
            *(float4*)&Bs[kr][nq] = vb;
        }
        __syncthreads();
        #pragma unroll
        for (int k = 0; k < 16; k++) {
            float4 a = *(const float4*)&As[k][ty * 4];
            float4 bv = *(const float4*)&Bs[k][tx * 4];
            float av[4] = {a.x, a.y, a.z, a.w};
            float bw[4] = {bv.x, bv.y, bv.z, bv.w};
            #pragma unroll
            for (int i = 0; i < 4; i++)
                #pragma unroll
                for (int j = 0; j < 4; j++)
                    acc[i][j] = fmaf(av[i], bw[j], acc[i][j]);
        }
        __syncthreads();
    }
    #pragma unroll
    for (int i = 0; i < 4; i++) {
        int gm = m0 + ty * 4 + i;
        if (gm < kT) {
            #pragma unroll
            for (int j = 0; j < 4; j++)
                C[(size_t)gm * kE + n0 + tx * 4 + j] = acc[i][j];
        }
    }
}

// ---------------- fused span kernel (pipelined, packed f32x2 GEMM) -------------
// Tile: 64 spans x 128 labels, K=1024 in chunks of 32. Double-buffered h1/W2.
// Inner GEMM uses fma.rn.f32x2 on label pairs: 16 FFMA2 per k per lane.
#define BUILD_CHUNK(kc_, p_) do {                                              \
    int k0_ = (kc_) * 32;                                                      \
    _Pragma("unroll")                                                          \
    for (int i_ = 0; i_ < 4; i_++) {                                           \
        int e_ = tid + 256 * i_;                                               \
        int kk_ = e_ >> 5, nq_ = (e_ & 31) * 4;                                \
        *(float4*)&w2s[p_][kk_][nq_] =                                         \
            *(const float4*)&W2[(size_t)(k0_ + kk_) * 128 + nq_];              \
    }                                                                          \
    int kg_ = k0_ + lane_k;                                                    \
    float b1v_ = b1[kg_], c1v_ = c1[kg_], v2v_ = V2[kg_];                      \
    _Pragma("unroll")                                                          \
    for (int i_ = 0; i_ < 8; i_++) {                                           \
        int m_ = mwarp + 8 * i_;                                               \
        int l_ = sL[m_], r_ = sR[m_];                                          \
        size_t rr_ = (size_t)r_ * kE + kg_, ll_ = (size_t)l_ * kE + kg_;       \
        size_t l1_ = (size_t)(l_ + 1) * kE + kg_;                              \
        size_t r1_ = (size_t)(r_ + 1) * kE + kg_;                              \
        float hl_ = A1f[rr_] - A1f[ll_] + A1b[l1_] - A1b[r1_] + b1v_;          \
        h1s[p_][m_][lane_k] = fmaxf(hl_, 0.f);                                 \
        float hv_ = Avf[rr_] - Avf[ll_] + Avb[l1_] - Avb[r1_] + c1v_;          \
        spl[i_] = fmaf(fmaxf(hv_, 0.f), v2v_, spl[i_]);                        \
    }                                                                          \
} while (0)

constexpr int kSpanSmem = (2 * 64 * 33 + 2 * 32 * 128) * 4;   // 49664 bytes

__global__ __launch_bounds__(256) void span_kernel(const float* __restrict__ W2,
                                                   const float* __restrict__ b1,
                                                   const float* __restrict__ b2,
                                                   const float* __restrict__ V2,
                                                   const float* __restrict__ c1,
                                                   const float* __restrict__ c2,
                                                   float* __restrict__ out)
{
    extern __shared__ __align__(16) float dyn[];
    float (*h1s)[64][33]  = (float (*)[64][33])dyn;               // 2 buffers
    float (*w2s)[32][128] = (float (*)[32][128])(dyn + 2 * 64 * 33);
    __shared__ int sL[64], sR[64];
    __shared__ float ssplit[64];

    int tid = threadIdx.x;
    int s0 = blockIdx.x * 64;
    if (tid < 64) {
        int s = s0 + tid;
        if (s < kS) { sL[tid] = g_L[s]; sR[tid] = g_R[s]; }
        else        { sL[tid] = 0;      sR[tid] = 1;      }
        ssplit[tid] = 0.f;
    }
    __syncthreads();

    const float* A1f = g_A1;
    const float* A1b = g_A1 + (size_t)kT * kE;
    const float* Avf = g_Av;
    const float* Avb = g_Av + (size_t)kT * kE;

    unsigned long long acc[4][4] = {};     // packed label-pairs: j = 2q, 2q+1
    float spl[8] = {};
    int lane_k = tid & 31;
    int mwarp  = tid >> 5;
    int tx = tid & 15, ty = tid >> 4;

    BUILD_CHUNK(0, 0);
    __syncthreads();

    for (int kc = 0; kc < 32; kc++) {
        int p = kc & 1;
        if (kc < 31) BUILD_CHUNK(kc + 1, p ^ 1);
        // GEMM: 64x128 += h1(64x32) * w2(32x128), packed f32x2
        #pragma unroll
        for (int k = 0; k < 32; k++) {
            ulonglong2 wA = *(const ulonglong2*)&w2s[p][k][tx * 8];
            ulonglong2 wB = *(const ulonglong2*)&w2s[p][k][tx * 8 + 4];
            #pragma unroll
            for (int i = 0; i < 4; i++) {
                float a = h1s[p][ty * 4 + i][k];
                unsigned long long aa = pack2(a, a);
                acc[i][0] = fma_f32x2(aa, wA.x, acc[i][0]);
                acc[i][1] = fma_f32x2(aa, wA.y, acc[i][1]);
                acc[i][2] = fma_f32x2(aa, wB.x, acc[i][2]);
                acc[i][3] = fma_f32x2(aa, wB.y, acc[i][3]);
            }
        }
        __syncthreads();
    }

    // reduce split partials (each warp owns spans m with m%8 == warp id)
    #pragma unroll
    for (int i = 0; i < 8; i++) {
        float v = spl[i];
        v += __shfl_down_sync(0xffffffffu, v, 16);
        v += __shfl_down_sync(0xffffffffu, v, 8);
        v += __shfl_down_sync(0xffffffffu, v, 4);
        v += __shfl_down_sync(0xffffffffu, v, 2);
        v += __shfl_down_sync(0xffffffffu, v, 1);
        if (lane_k == 0) ssplit[mwarp + 8 * i] = v;
    }
    __syncthreads();

    float c2v = c2[0];
    #pragma unroll
    for (int i = 0; i < 4; i++) {
        int s = s0 + ty * 4 + i;
        if (s < kS) {
            float* po = out + (size_t)s * 129;
            #pragma unroll
            for (int q = 0; q < 4; q++) {
                float2 v = unpack2(acc[i][q]);
                int n = tx * 8 + 2 * q;
                po[n]     = v.x + b2[n];
                po[n + 1] = v.y + b2[n + 1];
            }
            if (tx == 0) po[128] = ssplit[ty * 4 + i] + c2v;
        }
    }
}

// ---------------- launch ----------------
extern "C" void kernel_launch(void* const* d_in, const int* in_sizes, int n_in,
                              void* d_out, int out_size)
{
    const int*   tag_ids  = (const int*)  d_in[0];
    const int*   word_ids = (const int*)  d_in[1];
    const float* tag_emb  = (const float*)d_in[2];
    const float* word_emb = (const float*)d_in[3];
    const float* Wf_ih    = (const float*)d_in[4];
    const float* Wf_hh    = (const float*)d_in[5];
    const float* bf       = (const float*)d_in[6];
    const float* Wb_ih    = (const float*)d_in[7];
    const float* Wb_hh    = (const float*)d_in[8];
    const float* bb       = (const float*)d_in[9];
    const float* W1       = (const float*)d_in[10];
    const float* b1       = (const float*)d_in[11];
    const float* W2       = (const float*)d_in[12];
    const float* b2       = (const float*)d_in[13];
    const float* V1       = (const float*)d_in[14];
    const float* c1       = (const float*)d_in[15];
    const float* V2       = (const float*)d_in[16];
    const float* c2       = (const float*)d_in[17];
    float* out = (float*)d_out;

    cudaFuncSetAttribute(span_kernel, cudaFuncAttributeMaxDynamicSharedMemorySize,
                         kSpanSmem);

    init_kernel<<<kT + (kS + 255) / 256, 256>>>(tag_ids, word_ids, tag_emb, word_emb);
    gx_gemm<<<dim3((kT + 63) / 64, kG / 64, 2), 256>>>(Wf_ih, bf, Wb_ih, bb);
    lstm_kernel<<<64, 512>>>(Wf_hh, Wb_hh);
    pre_gemm<<<dim3((kT + 63) / 64, kE / 64, 4), 256>>>(W1, V1);
    span_kernel<<<(kS + 63) / 64, 256, kSpanSmem>>>(W2, b1, b2, V2, c1, c2, out);
}

// round 9
// speedup vs baseline: 1.0255x; 1.0255x over previous
#include <cuda_runtime.h>
#include <cuda_bf16.h>
#include <math.h>

// Problem constants
constexpr int kT = 386;       // LSTM positions (SENT_LEN + 2)
constexpr int kH = 512;       // hidden dim
constexpr int kG = 2048;      // 4*H gates
constexpr int kE = 1024;      // enc dim (2H)
constexpr int kS = 73920;     // number of spans = 385*384/2

// ---------------- scratch (device globals; no allocation) ----------------
__device__ float g_x [kT * kH];           // embedded input [T,512]
__device__ float g_gx[2 * kT * kG];       // x@Wih^T + b per direction [2][T][2048]
__device__ float g_h [2 * kT * kH];       // fwd/bwd hidden states [2][T][512]
__device__ float g_A1[2 * kT * kE];       // fwd@W1_top / bwd@W1_bot  [2][T][1024]
__device__ float g_Av[2 * kT * kE];       // fwd@V1_top / bwd@V1_bot  [2][T][1024]
__device__ int   g_L[kS];
__device__ int   g_R[kS];
__device__ unsigned g_flag[2][32][32];    // per-CTA monotonic step flag, 128B apart

// ---------------- fast math helpers ----------------
__device__ __forceinline__ float fast_ex2(float x) {
    float r; asm("ex2.approx.ftz.f32 %0, %1;" : "=f"(r) : "f"(x)); return r;
}
__device__ __forceinline__ float fast_rcp(float x) {
    float r; asm("rcp.approx.ftz.f32 %0, %1;" : "=f"(r) : "f"(x)); return r;
}
__device__ __forceinline__ float fsig(float x) {
    return fast_rcp(1.f + fast_ex2(-1.44269504f * x));
}
__device__ __forceinline__ float ftanh(float x) {
    return fmaf(2.f, fsig(2.f * x), -1.f);
}

// packed fp32x2 helpers (Blackwell FFMA2)
__device__ __forceinline__ unsigned long long fma_f32x2(unsigned long long a,
                                                        unsigned long long b,
                                                        unsigned long long c) {
    unsigned long long d;
    asm("fma.rn.f32x2 %0, %1, %2, %3;" : "=l"(d) : "l"(a), "l"(b), "l"(c));
    return d;
}
__device__ __forceinline__ unsigned long long pack2(float lo, float hi) {
    unsigned long long d;
    asm("mov.b64 %0, {%1, %2};" : "=l"(d) : "f"(lo), "f"(hi));
    return d;
}
__device__ __forceinline__ float2 unpack2(unsigned long long v) {
    float lo, hi;
    asm("mov.b64 {%0, %1}, %2;" : "=f"(lo), "=f"(hi) : "l"(v));
    return make_float2(lo, hi);
}

// ---------------- init: embeddings gather + span index tables + flag reset ----
__global__ void init_kernel(const int* __restrict__ tag_ids,
                            const int* __restrict__ word_ids,
                            const float* __restrict__ tag_emb,
                            const float* __restrict__ word_emb)
{
    int b = blockIdx.x, tid = threadIdx.x;
    if (b == 0) {
        unsigned* f = &g_flag[0][0][0];
        for (int i = tid; i < 2 * 32 * 32; i += 256) f[i] = 0u;
    }
    if (b < kT) {
        int t = b;
        int tg = tag_ids[t], wd = word_ids[t];
        for (int i = tid; i < kH; i += 256) {
            float v = (i < 128) ? tag_emb[tg * 128 + i] : word_emb[wd * 384 + (i - 128)];
            g_x[t * kH + i] = v;
        }
    } else {
        int s = (b - kT) * 256 + tid;
        if (s < kS) {
            // invert triangular index: off(l) = (769*l - l*l)/2
            int l = (int)((769.0 - sqrt((double)(591361 - 8 * s))) * 0.5);
            if (l < 0) l = 0; if (l > 383) l = 383;
            while (l < 383 && (769 * (l + 1) - (l + 1) * (l + 1)) / 2 <= s) l++;
            while (l > 0 && (769 * l - l * l) / 2 > s) l--;
            int off = (769 * l - l * l) / 2;
            g_L[s] = l;
            g_R[s] = l + 1 + (s - off);
        }
    }
}

// ---------------- gx GEMM: gx[dir] = x @ Wih^T + b   (NT layout) ----------------
// M=386, N=2048, K=512. A=[M,K] row-major, B=[N,K] row-major.
__global__ __launch_bounds__(256) void gx_gemm(const float* __restrict__ Wf,
                                               const float* __restrict__ bfv,
                                               const float* __restrict__ Wb,
                                               const float* __restrict__ bbv)
{
    int dir = blockIdx.z;
    const float* B    = dir ? Wb : Wf;
    const float* bias = dir ? bbv : bfv;
    const float* A = g_x;
    float* C = g_gx + (size_t)dir * kT * kG;

    int tid = threadIdx.x;
    int m0 = blockIdx.x * 64, n0 = blockIdx.y * 64;
    __shared__ __align__(16) float As[16][68];
    __shared__ __align__(16) float Bs[16][68];
    float acc[4][4] = {};
    int tx = tid & 15, ty = tid >> 4;

    for (int k0 = 0; k0 < kH; k0 += 16) {
        int mr = tid >> 2, kq = (tid & 3) * 4;
        int gm = m0 + mr;
        float4 va = (gm < kT) ? *(const float4*)&A[(size_t)gm * kH + k0 + kq]
                              : make_float4(0.f, 0.f, 0.f, 0.f);
        As[kq + 0][mr] = va.x; As[kq + 1][mr] = va.y;
        As[kq + 2][mr] = va.z; As[kq + 3][mr] = va.w;
        float4 vb = *(const float4*)&B[(size_t)(n0 + mr) * kH + k0 + kq];
        Bs[kq + 0][mr] = vb.x; Bs[kq + 1][mr] = vb.y;
        Bs[kq + 2][mr] = vb.z; Bs[kq + 3][mr] = vb.w;
        __syncthreads();
        #pragma unroll
        for (int k = 0; k < 16; k++) {
            float4 a = *(const float4*)&As[k][ty * 4];
            float4 bv = *(const float4*)&Bs[k][tx * 4];
            float av[4] = {a.x, a.y, a.z, a.w};
            float bw[4] = {bv.x, bv.y, bv.z, bv.w};
            #pragma unroll
            for (int i = 0; i < 4; i++)
                #pragma unroll
                for (int j = 0; j < 4; j++)
                    acc[i][j] = fmaf(av[i], bw[j], acc[i][j]);
        }
        __syncthreads();
    }
    #pragma unroll
    for (int i = 0; i < 4; i++) {
        int gm = m0 + ty * 4 + i;
        if (gm < kT) {
            #pragma unroll
            for (int j = 0; j < 4; j++) {
                int n = n0 + tx * 4 + j;
                C[(size_t)gm * kG + n] = acc[i][j] + bias[j + n0 + tx * 4 - tx * 4 + tx * 4];
            }
        }
    }
}

// ---------------- persistent bidirectional LSTM ----------------
// 64 CTAs: CTAs [0,32) = forward, [32,64) = backward. Each CTA owns 16 hidden
// units (64 gate rows); Whh slice in registers as packed f32x2 pairs.
// Sync: per-producer-CTA monotonic flag (128B apart). Producer: bar.sync +
// tid0 st.release flag=step+1. Consumer: warp lanes 0/16 poll only the flag
// of the CTA producing their h slice (ld.acquire), __syncwarp, then load h.
__global__ __launch_bounds__(512, 1) void lstm_kernel(const float* __restrict__ Wfhh,
                                                      const float* __restrict__ Wbhh)
{
    int tid = threadIdx.x;
    int dir = blockIdx.x >> 5;
    int cta = blockIdx.x & 31;
    int lr  = tid >> 3;      // local gate row 0..63
    int sl  = tid & 7;       // slice within row
    int gate = lr >> 4, u = lr & 15;
    int ug  = cta * 16 + u;
    int row = gate * kH + ug;

    const float* W = (dir ? Wbhh : Wfhh) + (size_t)row * kH;
    ulonglong2 w2r[16];
    int koff[16];
    #pragma unroll
    for (int m = 0; m < 16; m++) {
        int ko = sl * 64 + ((4 * m + 4 * sl) & 63);   // bank-rotated k offset
        koff[m] = ko;
        w2r[m] = *(const ulonglong2*)&W[ko];
    }

    __shared__ __align__(16) float sh_h[kH];
    __shared__ float sh_g[64];
    __shared__ float sh_c[16];
    if (tid < 16) sh_c[tid] = 0.f;

    float* hbase = g_h + (size_t)dir * kT * kH;
    const float* gxbase = g_gx + (size_t)dir * kT * kG;
    unsigned* myflag   = &g_flag[dir][cta][0];
    unsigned* peerflag = &g_flag[dir][tid >> 4][0];   // producer of h element tid
    int ugl = cta * 16 + (tid & 15);

    for (int step = 0; step < kT; step++) {
        int t = dir ? (kT - 1 - step) : step;

        // issue gx loads for this step first; they complete under the flag poll
        float4 gxv;
        if (tid < 16) {
            const float* gx = gxbase + (size_t)t * kG + ugl;
            gxv.x = __ldcg(gx);
            gxv.y = __ldcg(gx + kH);
            gxv.z = __ldcg(gx + 2 * kH);
            gxv.w = __ldcg(gx + 3 * kH);
        }

        if (step == 0) {
            sh_h[tid] = 0.f;
        } else {
            if ((tid & 15) == 0) {
                unsigned v;
                do {
                    asm volatile("ld.acquire.gpu.u32 %0, [%1];"
                                 : "=r"(v) : "l"(peerflag) : "memory");
                } while (v < (unsigned)step);
            }
            __syncwarp();
            int tp = dir ? t + 1 : t - 1;
            sh_h[tid] = __ldcg(&hbase[(size_t)tp * kH + tid]);
        }
        __syncthreads();

        // packed gemv: 4 independent f32x2 accumulator chains
        unsigned long long a0 = 0ull, a1 = 0ull, a2 = 0ull, a3 = 0ull;
        #pragma unroll
        for (int m = 0; m < 16; m += 2) {
            ulonglong2 h0 = *(const ulonglong2*)&sh_h[koff[m]];
            ulonglong2 h1 = *(const ulonglong2*)&sh_h[koff[m + 1]];
            a0 = fma_f32x2(w2r[m].x,     h0.x, a0);
            a1 = fma_f32x2(w2r[m].y,     h0.y, a1);
            a2 = fma_f32x2(w2r[m + 1].x, h1.x, a2);
            a3 = fma_f32x2(w2r[m + 1].y, h1.y, a3);
        }
        float2 f0 = unpack2(a0), f1 = unpack2(a1), f2 = unpack2(a2), f3 = unpack2(a3);
        float acc = ((f0.x + f0.y) + (f1.x + f1.y)) + ((f2.x + f2.y) + (f3.x + f3.y));
        acc += __shfl_down_sync(0xffffffffu, acc, 4, 8);
        acc += __shfl_down_sync(0xffffffffu, acc, 2, 8);
        acc += __shfl_down_sync(0xffffffffu, acc, 1, 8);
        if (sl == 0) sh_g[lr] = acc;
        __syncthreads();

        if (tid < 16) {
            float gi = gxv.x + sh_g[tid];
            float gf = gxv.y + sh_g[16 + tid];
            float gg = gxv.z + sh_g[32 + tid];
            float go = gxv.w + sh_g[48 + tid];
            float si = fsig(gi);
            float sf = fsig(gf);
            float so = fsig(go);
            float c = sf * sh_c[tid] + si * ftanh(gg);
            sh_c[tid] = c;
            float h = so * ftanh(c);
            __stcg(&hbase[(size_t)t * kH + ugl], h);
        }
        __syncthreads();
        if (step < kT - 1 && tid == 0) {
            // publish: syncthreads above gives HB from the 16 h-stores to tid0;
            // release store makes them (and the flag) visible at gpu scope.
            asm volatile("st.release.gpu.u32 [%0], %1;"
                         :: "l"(myflag), "r"((unsigned)(step + 1)) : "memory");
        }
        // no trailing syncthreads: next iteration's poll/sh_h write is ordered
        // by the syncthreads above (sh_h not touched between).
    }
}

// ---------------- A-table GEMMs: A[dir] = h[dir] @ Wtab[dir_half]  (NN) --------
// M=386, N=1024, K=512. B=[K,N] row-major (n contiguous).
__global__ __launch_bounds__(256) void pre_gemm(const float* __restrict__ W1,
                                                const float* __restrict__ V1)
{
    int dir = blockIdx.z & 1, tab = blockIdx.z >> 1;
    const float* A = g_h + (size_t)dir * kT * kH;
    const float* B = (tab ? V1 : W1) + (size_t)dir * kH * kE;
    float* C = (tab ? g_Av : g_A1) + (size_t)dir * kT * kE;

    int tid = threadIdx.x;
    int m0 = blockIdx.x * 64, n0 = blockIdx.y * 64;
    __shared__ __align__(16) float As[16][68];
    __shared__ __align__(16) float Bs[16][68];
    float acc[4][4] = {};
    int tx = tid & 15, ty = tid >> 4;

    for (int k0 = 0; k0 < kH; k0 += 16) {
        {
            int mr = tid >> 2, kq = (tid & 3) * 4;
            int gm = m0 + mr;
            float4 va = (gm < kT) ? *(const float4*)&A[(size_t)gm * kH + k0 + kq]
                                  : make_float4(0.f, 0.f, 0.f, 0.f);
            As[kq + 0][mr] = va.x; As[kq + 1][mr] = va.y;
            As[kq + 2][mr] = va.z; As[kq + 3][mr] = va.w;
        }
        {
            int kr = tid >> 4, nq = (tid & 15) * 4;
            float4 vb = *(const float4*)&B[(size_t)(k0 + kr) * kE + n0 + nq];
            *(float4*)&Bs[kr][nq] = vb;
        }
        __syncthreads();
        #pragma unroll
        for (int k = 0; k < 16; k++) {
            float4 a = *(const float4*)&As[k][ty * 4];
            float4 bv = *(const float4*)&Bs[k][tx * 4];
            float av[4] = {a.x, a.y, a.z, a.w};
            float bw[4] = {bv.x, bv.y, bv.z, bv.w};
            #pragma unroll
            for (int i = 0; i < 4; i++)
                #pragma unroll
                for (int j = 0; j < 4; j++)
                    acc[i][j] = fmaf(av[i], bw[j], acc[i][j]);
        }
        __syncthreads();
    }
    #pragma unroll
    for (int i = 0; i < 4; i++) {
        int gm = m0 + ty * 4 + i;
        if (gm < kT) {
            #pragma unroll
            for (int j = 0; j < 4; j++)
                C[(size_t)gm * kE + n0 + tx * 4 + j] = acc[i][j];
        }
    }
}

// ---------------- fused span kernel (pipelined, packed f32x2 GEMM) -------------
// Tile: 64 spans x 128 labels, K=1024 in chunks of 32. Double-buffered h1/W2.
#define BUILD_CHUNK(kc_, p_) do {                                              \
    int k0_ = (kc_) * 32;                                                      \
    _Pragma("unroll")                                                          \
    for (int i_ = 0; i_ < 4; i_++) {                                           \
        int e_ = tid + 256 * i_;                                               \
        int kk_ = e_ >> 5, nq_ = (e_ & 31) * 4;                                \
        *(float4*)&w2s[p_][kk_][nq_] =                                         \
            *(const float4*)&W2[(size_t)(k0_ + kk_) * 128 + nq_];              \
    }                                                                          \
    int kg_ = k0_ + lane_k;                                                    \
    float b1v_ = b1[kg_], c1v_ = c1[kg_], v2v_ = V2[kg_];                      \
    _Pragma("unroll")                                                          \
    for (int i_ = 0; i_ < 8; i_++) {                                           \
        int m_ = mwarp + 8 * i_;                                               \
        int l_ = sL[m_], r_ = sR[m_];                                          \
        size_t rr_ = (size_t)r_ * kE + kg_, ll_ = (size_t)l_ * kE + kg_;       \
        size_t l1_ = (size_t)(l_ + 1) * kE + kg_;                              \
        size_t r1_ = (size_t)(r_ + 1) * kE + kg_;                              \
        float hl_ = A1f[rr_] - A1f[ll_] + A1b[l1_] - A1b[r1_] + b1v_;          \
        h1s[p_][m_][lane_k] = fmaxf(hl_, 0.f);                                 \
        float hv_ = Avf[rr_] - Avf[ll_] + Avb[l1_] - Avb[r1_] + c1v_;          \
        spl[i_] = fmaf(fmaxf(hv_, 0.f), v2v_, spl[i_]);                        \
    }                                                                          \
} while (0)

constexpr int kSpanSmem = (2 * 64 * 33 + 2 * 32 * 128) * 4;   // 49664 bytes

__global__ __launch_bounds__(256) void span_kernel(const float* __restrict__ W2,
                                                   const float* __restrict__ b1,
                                                   const float* __restrict__ b2,
                                                   const float* __restrict__ V2,
                                                   const float* __restrict__ c1,
                                                   const float* __restrict__ c2,
                                                   float* __restrict__ out)
{
    extern __shared__ __align__(16) float dyn[];
    float (*h1s)[64][33]  = (float (*)[64][33])dyn;               // 2 buffers
    float (*w2s)[32][128] = (float (*)[32][128])(dyn + 2 * 64 * 33);
    __shared__ int sL[64], sR[64];
    __shared__ float ssplit[64];

    int tid = threadIdx.x;
    int s0 = blockIdx.x * 64;
    if (tid < 64) {
        int s = s0 + tid;
        if (s < kS) { sL[tid] = g_L[s]; sR[tid] = g_R[s]; }
        else        { sL[tid] = 0;      sR[tid] = 1;      }
        ssplit[tid] = 0.f;
    }
    __syncthreads();

    const float* A1f = g_A1;
    const float* A1b = g_A1 + (size_t)kT * kE;
    const float* Avf = g_Av;
    const float* Avb = g_Av + (size_t)kT * kE;

    unsigned long long acc[4][4] = {};     // packed label-pairs: j = 2q, 2q+1
    float spl[8] = {};
    int lane_k = tid & 31;
    int mwarp  = tid >> 5;
    int tx = tid & 15, ty = tid >> 4;

    BUILD_CHUNK(0, 0);
    __syncthreads();

    for (int kc = 0; kc < 32; kc++) {
        int p = kc & 1;
        if (kc < 31) BUILD_CHUNK(kc + 1, p ^ 1);
        // GEMM: 64x128 += h1(64x32) * w2(32x128), packed f32x2
        #pragma unroll
        for (int k = 0; k < 32; k++) {
            ulonglong2 wA = *(const ulonglong2*)&w2s[p][k][tx * 8];
            ulonglong2 wB = *(const ulonglong2*)&w2s[p][k][tx * 8 + 4];
            #pragma unroll
            for (int i = 0; i < 4; i++) {
                float a = h1s[p][ty * 4 + i][k];
                unsigned long long aa = pack2(a, a);
                acc[i][0] = fma_f32x2(aa, wA.x, acc[i][0]);
                acc[i][1] = fma_f32x2(aa, wA.y, acc[i][1]);
                acc[i][2] = fma_f32x2(aa, wB.x, acc[i][2]);
                acc[i][3] = fma_f32x2(aa, wB.y, acc[i][3]);
            }
        }
        __syncthreads();
    }

    // reduce split partials (each warp owns spans m with m%8 == warp id)
    #pragma unroll
    for (int i = 0; i < 8; i++) {
        float v = spl[i];
        v += __shfl_down_sync(0xffffffffu, v, 16);
        v += __shfl_down_sync(0xffffffffu, v, 8);
        v += __shfl_down_sync(0xffffffffu, v, 4);
        v += __shfl_down_sync(0xffffffffu, v, 2);
        v += __shfl_down_sync(0xffffffffu, v, 1);
        if (lane_k == 0) ssplit[mwarp + 8 * i] = v;
    }
    __syncthreads();

    float c2v = c2[0];
    #pragma unroll
    for (int i = 0; i < 4; i++) {
        int s = s0 + ty * 4 + i;
        if (s < kS) {
            float* po = out + (size_t)s * 129;
            #pragma unroll
            for (int q = 0; q < 4; q++) {
                float2 v = unpack2(acc[i][q]);
                int n = tx * 8 + 2 * q;
                po[n]     = v.x + b2[n];
                po[n + 1] = v.y + b2[n + 1];
            }
            if (tx == 0) po[128] = ssplit[ty * 4 + i] + c2v;
        }
    }
}

// ---------------- launch ----------------
extern "C" void kernel_launch(void* const* d_in, const int* in_sizes, int n_in,
                              void* d_out, int out_size)
{
    const int*   tag_ids  = (const int*)  d_in[0];
    const int*   word_ids = (const int*)  d_in[1];
    const float* tag_emb  = (const float*)d_in[2];
    const float* word_emb = (const float*)d_in[3];
    const float* Wf_ih    = (const float*)d_in[4];
    const float* Wf_hh    = (const float*)d_in[5];
    const float* bf       = (const float*)d_in[6];
    const float* Wb_ih    = (const float*)d_in[7];
    const float* Wb_hh    = (const float*)d_in[8];
    const float* bb       = (const float*)d_in[9];
    const float* W1       = (const float*)d_in[10];
    const float* b1       = (const float*)d_in[11];
    const float* W2       = (const float*)d_in[12];
    const float* b2       = (const float*)d_in[13];
    const float* V1       = (const float*)d_in[14];
    const float* c1       = (const float*)d_in[15];
    const float* V2       = (const float*)d_in[16];
    const float* c2       = (const float*)d_in[17];
    float* out = (float*)d_out;

    cudaFuncSetAttribute(span_kernel, cudaFuncAttributeMaxDynamicSharedMemorySize,
                         kSpanSmem);

    init_kernel<<<kT + (kS + 255) / 256, 256>>>(tag_ids, word_ids, tag_emb, word_emb);
    gx_gemm<<<dim3((kT + 63) / 64, kG / 64, 2), 256>>>(Wf_ih, bf, Wb_ih, bb);
    lstm_kernel<<<64, 512>>>(Wf_hh, Wb_hh);
    pre_gemm<<<dim3((kT + 63) / 64, kE / 64, 4), 256>>>(W1, V1);
    span_kernel<<<(kS + 63) / 64, 256, kSpanSmem>>>(W2, b1, b2, V2, c1, c2, out);
}